// round 1
// baseline (speedup 1.0000x reference)
#include <cuda_runtime.h>
#include <math.h>

#define NB 25
#define BDIM 4096
#define D 1024
#define ROWSTRIDE (NB * D)   // 25600
#define NSQ 12               // number of Gram-matrix squarings
#define NMAT (2 * NB)        // 50 matrices total (W1s then W2s)

// ---------------- scratch (static device globals; no cudaMalloc allowed) ----
__device__ float g_G [(size_t)NMAT * D * D];   // original Gram matrices (200MB)
__device__ float g_P0[(size_t)NMAT * D * D];   // ping
__device__ float g_P1[(size_t)NMAT * D * D];   // pong
__device__ float g_h [(size_t)BDIM * NB * D];  // hidden activations (420MB)
__device__ float g_invt[NMAT];
__device__ float g_v  [NMAT * D];
__device__ float g_gv [NMAT * D];
__device__ float g_is [NMAT];                  // 1/sigma per matrix

// ---------------------------------------------------------------------------
// C[m] = s^2 * A[m]^T A[m], A row-major [D x D]. Used for Gram build (s=1)
// and for trace-normalized squaring (P symmetric => P^T P = P^2).
// ---------------------------------------------------------------------------
__global__ void __launch_bounds__(256) k_ata(const float* __restrict__ Abase,
                                             float* __restrict__ Cbase,
                                             const float* __restrict__ invt)
{
    const int m = blockIdx.z;
    const float* A = Abase + (size_t)m * D * D;
    float* C = Cbase + (size_t)m * D * D;
    const float s = invt ? invt[m] : 1.0f;

    __shared__ float As[32][132];
    __shared__ float Bs[32][132];

    const int tid = threadIdx.x;
    const int i0 = blockIdx.y * 128;
    const int j0 = blockIdx.x * 128;
    const int ty = tid >> 4, tx = tid & 15;

    float acc[8][8];
#pragma unroll
    for (int u = 0; u < 8; u++)
#pragma unroll
        for (int v = 0; v < 8; v++) acc[u][v] = 0.0f;

    for (int k0 = 0; k0 < D; k0 += 32) {
#pragma unroll
        for (int t = 0; t < 4; t++) {
            int l = tid + t * 256;          // 0..1023
            int kr = l >> 5;                // 0..31
            int cc = (l & 31) << 2;         // 0..124
            const float* rowp = &A[(size_t)(k0 + kr) * D];
            *(float4*)&As[kr][cc] = *(const float4*)&rowp[i0 + cc];
            *(float4*)&Bs[kr][cc] = *(const float4*)&rowp[j0 + cc];
        }
        __syncthreads();
#pragma unroll
        for (int k = 0; k < 32; k++) {
            float a[8], b[8];
            *(float4*)&a[0] = *(const float4*)&As[k][ty * 8];
            *(float4*)&a[4] = *(const float4*)&As[k][ty * 8 + 4];
            *(float4*)&b[0] = *(const float4*)&Bs[k][tx * 8];
            *(float4*)&b[4] = *(const float4*)&Bs[k][tx * 8 + 4];
#pragma unroll
            for (int u = 0; u < 8; u++)
#pragma unroll
                for (int v = 0; v < 8; v++)
                    acc[u][v] = fmaf(a[u], b[v], acc[u][v]);
        }
        __syncthreads();
    }
    const float s2 = s * s;
#pragma unroll
    for (int u = 0; u < 8; u++)
#pragma unroll
        for (int v = 0; v < 8; v++)
            C[(size_t)(i0 + ty * 8 + u) * D + j0 + tx * 8 + v] = acc[u][v] * s2;
}

// ---------------------------------------------------------------------------
// Fused MLP GEMM: Out[b, n, c] = act( (X[b, n, :] @ W[n]) * invsig[n] + bias[n, c] )
// X rows have stride ROWSTRIDE (layout [B, NB, D]). W[n] row-major [D, D].
// ---------------------------------------------------------------------------
__global__ void __launch_bounds__(256) k_mlp(const float* __restrict__ X,
                                             const float* __restrict__ W,
                                             const float* __restrict__ bias,
                                             const float* __restrict__ invsig,
                                             float* __restrict__ Out,
                                             int do_gelu)
{
    const int n = blockIdx.z;
    const float* A  = X + (size_t)n * D;
    const float* Bw = W + (size_t)n * D * D;
    const float s = invsig[n];

    __shared__ float As[32][132];
    __shared__ float Bs[32][132];

    const int tid = threadIdx.x;
    const int r0 = blockIdx.y * 128;   // batch block
    const int c0 = blockIdx.x * 128;   // output-channel block
    const int ty = tid >> 4, tx = tid & 15;

    float acc[8][8];
#pragma unroll
    for (int u = 0; u < 8; u++)
#pragma unroll
        for (int v = 0; v < 8; v++) acc[u][v] = 0.0f;

    for (int k0 = 0; k0 < D; k0 += 32) {
        // A tile: 128 batch rows x 32 k, transposed into As[k][row]
#pragma unroll
        for (int t = 0; t < 4; t++) {
            int l = tid + t * 256;
            int r = l >> 3;             // 0..127
            int kc = (l & 7) << 2;      // 0,4,...,28
            float4 v4 = *(const float4*)&A[(size_t)(r0 + r) * ROWSTRIDE + k0 + kc];
            As[kc + 0][r] = v4.x;
            As[kc + 1][r] = v4.y;
            As[kc + 2][r] = v4.z;
            As[kc + 3][r] = v4.w;
        }
        // B tile: 32 k rows x 128 cols, natural layout
#pragma unroll
        for (int t = 0; t < 4; t++) {
            int l = tid + t * 256;
            int kr = l >> 5;
            int cc = (l & 31) << 2;
            *(float4*)&Bs[kr][cc] = *(const float4*)&Bw[(size_t)(k0 + kr) * D + c0 + cc];
        }
        __syncthreads();
#pragma unroll
        for (int k = 0; k < 32; k++) {
            float a[8], b[8];
            *(float4*)&a[0] = *(const float4*)&As[k][ty * 8];
            *(float4*)&a[4] = *(const float4*)&As[k][ty * 8 + 4];
            *(float4*)&b[0] = *(const float4*)&Bs[k][tx * 8];
            *(float4*)&b[4] = *(const float4*)&Bs[k][tx * 8 + 4];
#pragma unroll
            for (int u = 0; u < 8; u++)
#pragma unroll
                for (int v = 0; v < 8; v++)
                    acc[u][v] = fmaf(a[u], b[v], acc[u][v]);
        }
        __syncthreads();
    }

#pragma unroll
    for (int u = 0; u < 8; u++) {
        const size_t r = r0 + ty * 8 + u;
#pragma unroll
        for (int v = 0; v < 8; v++) {
            const int c = c0 + tx * 8 + v;
            float val = acc[u][v] * s + bias[(size_t)n * D + c];
            if (do_gelu)
                val = 0.5f * val * (1.0f + erff(val * 0.70710678118654752f));
            Out[r * ROWSTRIDE + (size_t)n * D + c] = val;
        }
    }
}

// ---------------------------------------------------------------------------
__global__ void __launch_bounds__(256) k_trace(const float* __restrict__ P,
                                               float* __restrict__ invt)
{
    const int m = blockIdx.x;
    const float* M = P + (size_t)m * D * D;
    __shared__ float red[256];
    float sum = 0.0f;
    for (int d = threadIdx.x; d < D; d += 256) sum += M[(size_t)d * D + d];
    red[threadIdx.x] = sum;
    __syncthreads();
    for (int off = 128; off > 0; off >>= 1) {
        if (threadIdx.x < off) red[threadIdx.x] += red[threadIdx.x + off];
        __syncthreads();
    }
    if (threadIdx.x == 0) invt[m] = 1.0f / red[0];
}

// v[m] = P[m] @ ones  (row sums)
__global__ void __launch_bounds__(256) k_rowsum(const float* __restrict__ P,
                                                float* __restrict__ v)
{
    const int m = blockIdx.y;
    const int r = blockIdx.x;
    const float* row = P + (size_t)m * D * D + (size_t)r * D;
    float4 x = *(const float4*)&row[threadIdx.x * 4];
    float sum = x.x + x.y + x.z + x.w;
    __shared__ float red[256];
    red[threadIdx.x] = sum;
    __syncthreads();
    for (int off = 128; off > 0; off >>= 1) {
        if (threadIdx.x < off) red[threadIdx.x] += red[threadIdx.x + off];
        __syncthreads();
    }
    if (threadIdx.x == 0) v[m * D + r] = red[0];
}

// gv[m] = G[m] @ v[m]
__global__ void __launch_bounds__(256) k_matvec(const float* __restrict__ G,
                                                const float* __restrict__ v,
                                                float* __restrict__ gv)
{
    const int m = blockIdx.y;
    const int r = blockIdx.x;
    const float* row = G + (size_t)m * D * D + (size_t)r * D;
    const float* vm = v + m * D;
    float4 a = *(const float4*)&row[threadIdx.x * 4];
    float4 b = *(const float4*)&vm[threadIdx.x * 4];
    float sum = a.x * b.x + a.y * b.y + a.z * b.z + a.w * b.w;
    __shared__ float red[256];
    red[threadIdx.x] = sum;
    __syncthreads();
    for (int off = 128; off > 0; off >>= 1) {
        if (threadIdx.x < off) red[threadIdx.x] += red[threadIdx.x + off];
        __syncthreads();
    }
    if (threadIdx.x == 0) gv[m * D + r] = red[0];
}

// is[m] = 1/sigma = sqrt( (v.v) / (v.Gv) )   since lambda_max = v.Gv / v.v
__global__ void __launch_bounds__(256) k_sigma(const float* __restrict__ v,
                                               const float* __restrict__ gv,
                                               float* __restrict__ is_)
{
    const int m = blockIdx.x;
    float num = 0.0f, den = 0.0f;
    for (int d = threadIdx.x; d < D; d += 256) {
        float vv = v[m * D + d];
        num += vv * gv[m * D + d];
        den += vv * vv;
    }
    __shared__ float rn[256], rd[256];
    rn[threadIdx.x] = num;
    rd[threadIdx.x] = den;
    __syncthreads();
    for (int off = 128; off > 0; off >>= 1) {
        if (threadIdx.x < off) {
            rn[threadIdx.x] += rn[threadIdx.x + off];
            rd[threadIdx.x] += rd[threadIdx.x + off];
        }
        __syncthreads();
    }
    if (threadIdx.x == 0) is_[m] = sqrtf(rd[0] / rn[0]);
}

// ---------------------------------------------------------------------------
extern "C" void kernel_launch(void* const* d_in, const int* in_sizes, int n_in,
                              void* d_out, int out_size)
{
    const float* x  = (const float*)d_in[0];   // [4096, 25, 1024]
    const float* w1 = (const float*)d_in[1];   // [25, 1024, 1024]
    const float* b1 = (const float*)d_in[2];   // [25, 1, 1024]
    const float* w2 = (const float*)d_in[3];   // [25, 1024, 1024]
    const float* b2 = (const float*)d_in[4];   // [25, 1, 1024]
    float* out = (float*)d_out;                // [4096, 25, 1024]

    float *G, *P0, *P1, *h, *invt, *v, *gv, *is_;
    cudaGetSymbolAddress((void**)&G,    g_G);
    cudaGetSymbolAddress((void**)&P0,   g_P0);
    cudaGetSymbolAddress((void**)&P1,   g_P1);
    cudaGetSymbolAddress((void**)&h,    g_h);
    cudaGetSymbolAddress((void**)&invt, g_invt);
    cudaGetSymbolAddress((void**)&v,    g_v);
    cudaGetSymbolAddress((void**)&gv,   g_gv);
    cudaGetSymbolAddress((void**)&is_,  g_is);

    const dim3 blk(256);

    // 1) Gram matrices G = W^T W for all 50 weight matrices
    k_ata<<<dim3(8, 8, NB), blk>>>(w1, G, nullptr);
    k_ata<<<dim3(8, 8, NB), blk>>>(w2, G + (size_t)NB * D * D, nullptr);

    // 2) Repeated trace-normalized squaring: P <- (P/tr)^2, 12 times
    const float* pin = G;
    float* pout = P0;
    for (int s = 0; s < NSQ; s++) {
        k_trace<<<NMAT, blk>>>(pin, invt);
        k_ata<<<dim3(8, 8, NMAT), blk>>>(pin, pout, invt);
        pin = pout;
        pout = (pout == P0) ? P1 : P0;
    }

    // 3) Rayleigh quotient on original G with converged eigenvector
    k_rowsum<<<dim3(D, NMAT), blk>>>(pin, v);
    k_matvec<<<dim3(D, NMAT), blk>>>(G, v, gv);
    k_sigma<<<NMAT, blk>>>(v, gv, is_);

    // 4) MLP: h = gelu(x @ W1/s1 + b1);  out = h @ W2/s2 + b2
    k_mlp<<<dim3(8, 32, NB), blk>>>(x, w1, b1, is_,      h,   1);
    k_mlp<<<dim3(8, 32, NB), blk>>>(h, w2, b2, is_ + NB, out, 0);
}

// round 2
// speedup vs baseline: 1.0008x; 1.0008x over previous
#include <cuda_runtime.h>
#include <math.h>

#define NB 25
#define BDIM 4096
#define D 1024
#define ROWSTRIDE (NB * D)   // 25600
#define NSQ 12               // number of Gram-matrix squarings
#define NMAT (2 * NB)        // 50 matrices total (W1s then W2s)

// ---------------- scratch (static device globals; no cudaMalloc allowed) ----
__device__ float g_G [(size_t)NMAT * D * D];   // original Gram matrices (200MB)
__device__ float g_P0[(size_t)NMAT * D * D];   // ping
__device__ float g_P1[(size_t)NMAT * D * D];   // pong
__device__ float g_h [(size_t)BDIM * NB * D];  // hidden activations (420MB)
__device__ float g_invt[NMAT];
__device__ float g_v  [NMAT * D];
__device__ float g_gv [NMAT * D];
__device__ float g_is [NMAT];                  // 1/sigma per matrix

// ---------------------------------------------------------------------------
// C[m] = s^2 * A[m]^T A[m], A row-major [D x D]. Used for Gram build (s=1)
// and for trace-normalized squaring (P symmetric => P^T P = P^2).
// ---------------------------------------------------------------------------
__global__ void __launch_bounds__(256) k_ata(const float* __restrict__ Abase,
                                             float* __restrict__ Cbase,
                                             const float* __restrict__ invt)
{
    const int m = blockIdx.z;
    const float* A = Abase + (size_t)m * D * D;
    float* C = Cbase + (size_t)m * D * D;
    const float s = invt ? invt[m] : 1.0f;

    __shared__ float As[32][132];
    __shared__ float Bs[32][132];

    const int tid = threadIdx.x;
    const int i0 = blockIdx.y * 128;
    const int j0 = blockIdx.x * 128;
    const int ty = tid >> 4, tx = tid & 15;

    float acc[8][8];
#pragma unroll
    for (int u = 0; u < 8; u++)
#pragma unroll
        for (int v = 0; v < 8; v++) acc[u][v] = 0.0f;

    for (int k0 = 0; k0 < D; k0 += 32) {
#pragma unroll
        for (int t = 0; t < 4; t++) {
            int l = tid + t * 256;          // 0..1023
            int kr = l >> 5;                // 0..31
            int cc = (l & 31) << 2;         // 0..124
            const float* rowp = &A[(size_t)(k0 + kr) * D];
            *(float4*)&As[kr][cc] = *(const float4*)&rowp[i0 + cc];
            *(float4*)&Bs[kr][cc] = *(const float4*)&rowp[j0 + cc];
        }
        __syncthreads();
#pragma unroll
        for (int k = 0; k < 32; k++) {
            float a[8], b[8];
            *(float4*)&a[0] = *(const float4*)&As[k][ty * 8];
            *(float4*)&a[4] = *(const float4*)&As[k][ty * 8 + 4];
            *(float4*)&b[0] = *(const float4*)&Bs[k][tx * 8];
            *(float4*)&b[4] = *(const float4*)&Bs[k][tx * 8 + 4];
#pragma unroll
            for (int u = 0; u < 8; u++)
#pragma unroll
                for (int v = 0; v < 8; v++)
                    acc[u][v] = fmaf(a[u], b[v], acc[u][v]);
        }
        __syncthreads();
    }
    const float s2 = s * s;
#pragma unroll
    for (int u = 0; u < 8; u++)
#pragma unroll
        for (int v = 0; v < 8; v++)
            C[(size_t)(i0 + ty * 8 + u) * D + j0 + tx * 8 + v] = acc[u][v] * s2;
}

// ---------------------------------------------------------------------------
// Fused MLP GEMM: Out[b, n, c] = act( (X[b, n, :] @ W[n]) * invsig[n] + bias[n, c] )
// X rows have stride ROWSTRIDE (layout [B, NB, D]). W[n] row-major [D, D].
// ---------------------------------------------------------------------------
__global__ void __launch_bounds__(256) k_mlp(const float* __restrict__ X,
                                             const float* __restrict__ W,
                                             const float* __restrict__ bias,
                                             const float* __restrict__ invsig,
                                             float* __restrict__ Out,
                                             int do_gelu)
{
    const int n = blockIdx.z;
    const float* A  = X + (size_t)n * D;
    const float* Bw = W + (size_t)n * D * D;
    const float s = invsig[n];

    __shared__ float As[32][132];
    __shared__ float Bs[32][132];

    const int tid = threadIdx.x;
    const int r0 = blockIdx.y * 128;   // batch block
    const int c0 = blockIdx.x * 128;   // output-channel block
    const int ty = tid >> 4, tx = tid & 15;

    float acc[8][8];
#pragma unroll
    for (int u = 0; u < 8; u++)
#pragma unroll
        for (int v = 0; v < 8; v++) acc[u][v] = 0.0f;

    for (int k0 = 0; k0 < D; k0 += 32) {
        // A tile: 128 batch rows x 32 k, transposed into As[k][row]
#pragma unroll
        for (int t = 0; t < 4; t++) {
            int l = tid + t * 256;
            int r = l >> 3;             // 0..127
            int kc = (l & 7) << 2;      // 0,4,...,28
            float4 v4 = *(const float4*)&A[(size_t)(r0 + r) * ROWSTRIDE + k0 + kc];
            As[kc + 0][r] = v4.x;
            As[kc + 1][r] = v4.y;
            As[kc + 2][r] = v4.z;
            As[kc + 3][r] = v4.w;
        }
        // B tile: 32 k rows x 128 cols, natural layout
#pragma unroll
        for (int t = 0; t < 4; t++) {
            int l = tid + t * 256;
            int kr = l >> 5;
            int cc = (l & 31) << 2;
            *(float4*)&Bs[kr][cc] = *(const float4*)&Bw[(size_t)(k0 + kr) * D + c0 + cc];
        }
        __syncthreads();
#pragma unroll
        for (int k = 0; k < 32; k++) {
            float a[8], b[8];
            *(float4*)&a[0] = *(const float4*)&As[k][ty * 8];
            *(float4*)&a[4] = *(const float4*)&As[k][ty * 8 + 4];
            *(float4*)&b[0] = *(const float4*)&Bs[k][tx * 8];
            *(float4*)&b[4] = *(const float4*)&Bs[k][tx * 8 + 4];
#pragma unroll
            for (int u = 0; u < 8; u++)
#pragma unroll
                for (int v = 0; v < 8; v++)
                    acc[u][v] = fmaf(a[u], b[v], acc[u][v]);
        }
        __syncthreads();
    }

#pragma unroll
    for (int u = 0; u < 8; u++) {
        const size_t r = r0 + ty * 8 + u;
#pragma unroll
        for (int v = 0; v < 8; v++) {
            const int c = c0 + tx * 8 + v;
            float val = acc[u][v] * s + bias[(size_t)n * D + c];
            if (do_gelu)
                val = 0.5f * val * (1.0f + erff(val * 0.70710678118654752f));
            Out[r * ROWSTRIDE + (size_t)n * D + c] = val;
        }
    }
}

// ---------------------------------------------------------------------------
__global__ void __launch_bounds__(256) k_trace(const float* __restrict__ P,
                                               float* __restrict__ invt)
{
    const int m = blockIdx.x;
    const float* M = P + (size_t)m * D * D;
    __shared__ float red[256];
    float sum = 0.0f;
    for (int d = threadIdx.x; d < D; d += 256) sum += M[(size_t)d * D + d];
    red[threadIdx.x] = sum;
    __syncthreads();
    for (int off = 128; off > 0; off >>= 1) {
        if (threadIdx.x < off) red[threadIdx.x] += red[threadIdx.x + off];
        __syncthreads();
    }
    if (threadIdx.x == 0) invt[m] = 1.0f / red[0];
}

// v[m] = P[m] @ ones  (row sums)
__global__ void __launch_bounds__(256) k_rowsum(const float* __restrict__ P,
                                                float* __restrict__ v)
{
    const int m = blockIdx.y;
    const int r = blockIdx.x;
    const float* row = P + (size_t)m * D * D + (size_t)r * D;
    float4 x = *(const float4*)&row[threadIdx.x * 4];
    float sum = x.x + x.y + x.z + x.w;
    __shared__ float red[256];
    red[threadIdx.x] = sum;
    __syncthreads();
    for (int off = 128; off > 0; off >>= 1) {
        if (threadIdx.x < off) red[threadIdx.x] += red[threadIdx.x + off];
        __syncthreads();
    }
    if (threadIdx.x == 0) v[m * D + r] = red[0];
}

// gv[m] = G[m] @ v[m]
__global__ void __launch_bounds__(256) k_matvec(const float* __restrict__ G,
                                                const float* __restrict__ v,
                                                float* __restrict__ gv)
{
    const int m = blockIdx.y;
    const int r = blockIdx.x;
    const float* row = G + (size_t)m * D * D + (size_t)r * D;
    const float* vm = v + m * D;
    float4 a = *(const float4*)&row[threadIdx.x * 4];
    float4 b = *(const float4*)&vm[threadIdx.x * 4];
    float sum = a.x * b.x + a.y * b.y + a.z * b.z + a.w * b.w;
    __shared__ float red[256];
    red[threadIdx.x] = sum;
    __syncthreads();
    for (int off = 128; off > 0; off >>= 1) {
        if (threadIdx.x < off) red[threadIdx.x] += red[threadIdx.x + off];
        __syncthreads();
    }
    if (threadIdx.x == 0) gv[m * D + r] = red[0];
}

// is[m] = 1/sigma = sqrt( (v.v) / (v.Gv) )   since lambda_max = v.Gv / v.v
__global__ void __launch_bounds__(256) k_sigma(const float* __restrict__ v,
                                               const float* __restrict__ gv,
                                               float* __restrict__ is_)
{
    const int m = blockIdx.x;
    float num = 0.0f, den = 0.0f;
    for (int d = threadIdx.x; d < D; d += 256) {
        float vv = v[m * D + d];
        num += vv * gv[m * D + d];
        den += vv * vv;
    }
    __shared__ float rn[256], rd[256];
    rn[threadIdx.x] = num;
    rd[threadIdx.x] = den;
    __syncthreads();
    for (int off = 128; off > 0; off >>= 1) {
        if (threadIdx.x < off) {
            rn[threadIdx.x] += rn[threadIdx.x + off];
            rd[threadIdx.x] += rd[threadIdx.x + off];
        }
        __syncthreads();
    }
    if (threadIdx.x == 0) is_[m] = sqrtf(rd[0] / rn[0]);
}

// ---------------------------------------------------------------------------
extern "C" void kernel_launch(void* const* d_in, const int* in_sizes, int n_in,
                              void* d_out, int out_size)
{
    const float* x  = (const float*)d_in[0];   // [4096, 25, 1024]
    const float* w1 = (const float*)d_in[1];   // [25, 1024, 1024]
    const float* b1 = (const float*)d_in[2];   // [25, 1, 1024]
    const float* w2 = (const float*)d_in[3];   // [25, 1024, 1024]
    const float* b2 = (const float*)d_in[4];   // [25, 1, 1024]
    float* out = (float*)d_out;                // [4096, 25, 1024]

    float *G, *P0, *P1, *h, *invt, *v, *gv, *is_;
    cudaGetSymbolAddress((void**)&G,    g_G);
    cudaGetSymbolAddress((void**)&P0,   g_P0);
    cudaGetSymbolAddress((void**)&P1,   g_P1);
    cudaGetSymbolAddress((void**)&h,    g_h);
    cudaGetSymbolAddress((void**)&invt, g_invt);
    cudaGetSymbolAddress((void**)&v,    g_v);
    cudaGetSymbolAddress((void**)&gv,   g_gv);
    cudaGetSymbolAddress((void**)&is_,  g_is);

    const dim3 blk(256);

    // 1) Gram matrices G = W^T W for all 50 weight matrices
    k_ata<<<dim3(8, 8, NB), blk>>>(w1, G, nullptr);
    k_ata<<<dim3(8, 8, NB), blk>>>(w2, G + (size_t)NB * D * D, nullptr);

    // 2) Repeated trace-normalized squaring: P <- (P/tr)^2, 12 times
    const float* pin = G;
    float* pout = P0;
    for (int s = 0; s < NSQ; s++) {
        k_trace<<<NMAT, blk>>>(pin, invt);
        k_ata<<<dim3(8, 8, NMAT), blk>>>(pin, pout, invt);
        pin = pout;
        pout = (pout == P0) ? P1 : P0;
    }

    // 3) Rayleigh quotient on original G with converged eigenvector
    k_rowsum<<<dim3(D, NMAT), blk>>>(pin, v);
    k_matvec<<<dim3(D, NMAT), blk>>>(G, v, gv);
    k_sigma<<<NMAT, blk>>>(v, gv, is_);

    // 4) MLP: h = gelu(x @ W1/s1 + b1);  out = h @ W2/s2 + b2
    k_mlp<<<dim3(8, 32, NB), blk>>>(x, w1, b1, is_,      h,   1);
    k_mlp<<<dim3(8, 32, NB), blk>>>(h, w2, b2, is_ + NB, out, 0);
}

// round 5
// speedup vs baseline: 1.9703x; 1.9687x over previous
#include <cuda_runtime.h>
#include <cuda_bf16.h>
#include <cstdint>
#include <math.h>

#define NB 25
#define BATCH 4096
#define DN 1024
#define RS (NB * DN)
#define NMAT (2 * NB)
#define MM ((size_t)DN * DN)
#define NSQ 12
#define BK 32
#define NKS (DN / BK)          // 32 k-stages
#define NSTG 3
#define RSE 40                 // smem row stride in bf16 (80B)
#define MATB (128 * RSE * 2)   // 10240 B per matrix tile
#define STGB (4 * MATB)        // 40960 B per stage
#define SMEM_BYTES (NSTG * STGB)

typedef __nv_bfloat16 bf16;

// ----------------------------- scratch -------------------------------------
__device__ bf16  g_xhi[(size_t)BATCH * RS];
__device__ bf16  g_xlo[(size_t)BATCH * RS];
__device__ bf16  g_wth[NMAT * MM];
__device__ bf16  g_wtl[NMAT * MM];
__device__ float g_G  [NMAT * MM];
__device__ bf16  g_P0h[NMAT * MM];
__device__ bf16  g_P0l[NMAT * MM];
__device__ bf16  g_P1h[NMAT * MM];
__device__ bf16  g_P1l[NMAT * MM];
__device__ bf16  g_hhi[(size_t)BATCH * RS];
__device__ bf16  g_hlo[(size_t)BATCH * RS];
__device__ float g_tr [(NSQ + 1) * NMAT];
__device__ float g_v  [NMAT * DN];
__device__ float g_gv [NMAT * DN];
__device__ float g_is [NMAT];

// ----------------------------- PTX helpers ---------------------------------
__device__ __forceinline__ uint32_t smem_u32(const void* p) {
    uint32_t a;
    asm("{ .reg .u64 t; cvta.to.shared.u64 t, %1; cvt.u32.u64 %0, t; }" : "=r"(a) : "l"(p));
    return a;
}
__device__ __forceinline__ void cp16(uint32_t s, const void* g) {
    asm volatile("cp.async.cg.shared.global [%0], [%1], 16;" :: "r"(s), "l"(g));
}
#define CP_COMMIT() asm volatile("cp.async.commit_group;" ::: "memory")
#define CP_WAIT(N)  asm volatile("cp.async.wait_group %0;" :: "n"(N) : "memory")

#define LDSM4(r0, r1, r2, r3, addr) \
    asm volatile("ldmatrix.sync.aligned.m8n8.x4.shared.b16 {%0,%1,%2,%3}, [%4];" \
        : "=r"(r0), "=r"(r1), "=r"(r2), "=r"(r3) : "r"(addr))

#define MMA16816(c, a, b) \
    asm volatile("mma.sync.aligned.m16n8k16.row.col.f32.bf16.bf16.f32 " \
        "{%0,%1,%2,%3}, {%4,%5,%6,%7}, {%8,%9}, {%0,%1,%2,%3};" \
        : "+f"((c)[0]), "+f"((c)[1]), "+f"((c)[2]), "+f"((c)[3]) \
        : "r"((a)[0]), "r"((a)[1]), "r"((a)[2]), "r"((a)[3]), "r"((b)[0]), "r"((b)[1]))

// ----------------------------- conversions ---------------------------------
__global__ void __launch_bounds__(256) conv_split(const float* __restrict__ in,
                                                  bf16* __restrict__ hi, bf16* __restrict__ lo)
{
    size_t i = ((size_t)blockIdx.x * 256 + threadIdx.x) * 4;
    float4 v = *(const float4*)(in + i);
    bf16 h0 = __float2bfloat16(v.x), h1 = __float2bfloat16(v.y);
    bf16 h2 = __float2bfloat16(v.z), h3 = __float2bfloat16(v.w);
    hi[i+0] = h0; hi[i+1] = h1; hi[i+2] = h2; hi[i+3] = h3;
    lo[i+0] = __float2bfloat16(v.x - __bfloat162float(h0));
    lo[i+1] = __float2bfloat16(v.y - __bfloat162float(h1));
    lo[i+2] = __float2bfloat16(v.z - __bfloat162float(h2));
    lo[i+3] = __float2bfloat16(v.w - __bfloat162float(h3));
}

__global__ void __launch_bounds__(256) conv_wT(const float* __restrict__ w,
                                               bf16* __restrict__ hi, bf16* __restrict__ lo)
{
    const int m = blockIdx.z;
    const float* W = w + (size_t)m * MM;
    bf16* Hi = hi + (size_t)m * MM;
    bf16* Lo = lo + (size_t)m * MM;
    __shared__ float t[32][33];
    const int r0 = blockIdx.y * 32, c0 = blockIdx.x * 32;
    const int tr = threadIdx.x >> 5, tc = threadIdx.x & 31;
#pragma unroll
    for (int i = 0; i < 4; i++)
        t[tr + 8 * i][tc] = W[(size_t)(r0 + tr + 8 * i) * DN + c0 + tc];
    __syncthreads();
#pragma unroll
    for (int i = 0; i < 4; i++) {
        int rr = tr + 8 * i;
        float v = t[tc][rr];
        bf16 h = __float2bfloat16(v);
        size_t o = (size_t)(c0 + rr) * DN + r0 + tc;
        Hi[o] = h;
        Lo[o] = __float2bfloat16(v - __bfloat162float(h));
    }
}

// ----------------------------- warp-MMA GEMM --------------------------------
// C[r][c] = scl * sum_k A[r][k] * B[c][k]   (both operands K-major)
// MODE 0: Gram   -> Cf (fp32) + Chi/Clo
// MODE 1: square -> Chi/Clo, scl = (1/tr)^2
// MODE 2: MLP1   -> Chi/Clo = gelu(C*is + b1)
// MODE 3: MLP2   -> Cf = C*is + b2
template <int MODE>
__global__ void __launch_bounds__(256, 1) gemm_k(
    const bf16* __restrict__ Ahi, const bf16* __restrict__ Alo, long lda, long aoffz,
    const bf16* __restrict__ Bhi, const bf16* __restrict__ Blo,
    float* __restrict__ Cf, bf16* __restrict__ Chi, bf16* __restrict__ Clo,
    long ldc, long coffz,
    const float* __restrict__ bias, const float* __restrict__ sc,
    const float* __restrict__ trin)
{
    extern __shared__ char smem[];
    const uint32_t sb = smem_u32(smem);

    const int tid = threadIdx.x;
    const int wid = tid >> 5, lane = tid & 31;
    const int wr = wid >> 1, wc = wid & 1;
    const int z = blockIdx.z;
    const int row0 = blockIdx.y * 128, col0 = blockIdx.x * 128;

    const bf16* Ah = Ahi + (size_t)z * aoffz + (size_t)row0 * lda;
    const bf16* Al = Alo + (size_t)z * aoffz + (size_t)row0 * lda;
    const bf16* Bh = Bhi + (size_t)z * MM + (size_t)col0 * DN;
    const bf16* Bl = Blo + (size_t)z * MM + (size_t)col0 * DN;

    const bf16* gbase[4] = {Ah, Al, Bh, Bl};
    const long  gstr [4] = {lda, lda, DN, DN};

    // ---- stage loader: 4 matrices x 128 rows x 32 bf16 (64B) each ----
    auto load_stage = [&](int st, int k0) {
        const uint32_t base = sb + (uint32_t)st * STGB;
        const int ch = tid & 3;
        const int rlo = tid >> 2;                 // 0..63
#pragma unroll
        for (int t = 0; t < 8; t++) {
            const int mat = t >> 1;
            const int r = ((t & 1) << 6) + rlo;   // 0..127
            cp16(base + (uint32_t)mat * MATB + (uint32_t)(r * 80 + ch * 16),
                 gbase[mat] + (long)r * gstr[mat] + k0 + ch * 8);
        }
        CP_COMMIT();
    };

    float acc[2][8][4];
#pragma unroll
    for (int mi = 0; mi < 2; mi++)
#pragma unroll
        for (int ni = 0; ni < 8; ni++)
#pragma unroll
            for (int q = 0; q < 4; q++) acc[mi][ni][q] = 0.0f;

    load_stage(0, 0);
    load_stage(1, BK);

    // ldmatrix lane address components
    const int arow = (lane & 7) + ((lane >> 3) & 1) * 8;
    const int acol = (lane >> 4) * 16;            // bytes
    const int brow = (lane & 7) + ((lane >> 4) & 1) * 8;
    const int bcol = ((lane >> 3) & 1) * 16;      // bytes

    for (int s = 0; s < NKS; s++) {
        if (s < NKS - 1) { CP_WAIT(1); } else { CP_WAIT(0); }
        __syncthreads();
        if (s + 2 < NKS) load_stage((s + 2) % NSTG, (s + 2) * BK);

        const uint32_t stb = sb + (uint32_t)(s % NSTG) * STGB;
        const uint32_t aBh = stb + (uint32_t)((wr * 32 + arow) * 80) + acol;
        const uint32_t aBl = aBh + MATB;
        const uint32_t bBh = stb + 2u * MATB + (uint32_t)((wc * 64 + brow) * 80) + bcol;
        const uint32_t bBl = bBh + MATB;

#pragma unroll
        for (int kk = 0; kk < 2; kk++) {
            const uint32_t ko = (uint32_t)(kk * 32);   // 16 bf16 = 32B
            uint32_t ah[2][4], al[2][4], bh[8][2], bl[8][2];
#pragma unroll
            for (int mi = 0; mi < 2; mi++) {
                LDSM4(ah[mi][0], ah[mi][1], ah[mi][2], ah[mi][3], aBh + ko + (uint32_t)(mi * 16 * 80));
                LDSM4(al[mi][0], al[mi][1], al[mi][2], al[mi][3], aBl + ko + (uint32_t)(mi * 16 * 80));
            }
#pragma unroll
            for (int p = 0; p < 4; p++) {
                LDSM4(bh[2*p][0], bh[2*p][1], bh[2*p+1][0], bh[2*p+1][1], bBh + ko + (uint32_t)(p * 16 * 80));
                LDSM4(bl[2*p][0], bl[2*p][1], bl[2*p+1][0], bl[2*p+1][1], bBl + ko + (uint32_t)(p * 16 * 80));
            }
            // term-major for ILP: hh, then hl, then lh
#pragma unroll
            for (int mi = 0; mi < 2; mi++)
#pragma unroll
                for (int ni = 0; ni < 8; ni++) MMA16816(acc[mi][ni], ah[mi], bh[ni]);
#pragma unroll
            for (int mi = 0; mi < 2; mi++)
#pragma unroll
                for (int ni = 0; ni < 8; ni++) MMA16816(acc[mi][ni], ah[mi], bl[ni]);
#pragma unroll
            for (int mi = 0; mi < 2; mi++)
#pragma unroll
                for (int ni = 0; ni < 8; ni++) MMA16816(acc[mi][ni], al[mi], bh[ni]);
        }
        __syncthreads();
    }

    // ------------------------------ epilogue -------------------------------
    float scl = 1.0f;
    if (MODE == 1) { float it = 1.0f / trin[z]; scl = it * it; }
    if (MODE >= 2) scl = sc[z];
    const int gID = lane >> 2, tg = lane & 3;

#pragma unroll
    for (int mi = 0; mi < 2; mi++)
#pragma unroll
        for (int ni = 0; ni < 8; ni++)
#pragma unroll
            for (int hf = 0; hf < 2; hf++) {
                const int r = row0 + wr * 32 + mi * 16 + gID + hf * 8;
                const int c = col0 + wc * 64 + ni * 8 + tg * 2;
                float v0 = acc[mi][ni][hf * 2 + 0] * scl;
                float v1 = acc[mi][ni][hf * 2 + 1] * scl;
                if (MODE >= 2) {
                    v0 += bias[z * DN + c];
                    v1 += bias[z * DN + c + 1];
                }
                if (MODE == 2) {
                    v0 = 0.5f * v0 * (1.0f + erff(v0 * 0.70710678118654752f));
                    v1 = 0.5f * v1 * (1.0f + erff(v1 * 0.70710678118654752f));
                }
                const size_t off = (size_t)z * coffz + (size_t)r * ldc + c;
                if (MODE == 0 || MODE == 3) {
                    float2 f2; f2.x = v0; f2.y = v1;
                    *(float2*)(Cf + off) = f2;
                }
                if (MODE <= 2) {
                    bf16 h0 = __float2bfloat16(v0);
                    bf16 h1 = __float2bfloat16(v1);
                    __nv_bfloat162 hh; hh.x = h0; hh.y = h1;
                    __nv_bfloat162 ll;
                    ll.x = __float2bfloat16(v0 - __bfloat162float(h0));
                    ll.y = __float2bfloat16(v1 - __bfloat162float(h1));
                    *(__nv_bfloat162*)(Chi + off) = hh;
                    *(__nv_bfloat162*)(Clo + off) = ll;
                }
            }
}

// --------------------------- small kernels ----------------------------------
__global__ void __launch_bounds__(256) k_trace_hl(const bf16* __restrict__ Ph,
                                                  const bf16* __restrict__ Pl,
                                                  float* __restrict__ out)
{
    const int m = blockIdx.x;
    float sum = 0.0f;
    for (int d = threadIdx.x; d < DN; d += 256) {
        size_t o = (size_t)m * MM + (size_t)d * DN + d;
        sum += __bfloat162float(Ph[o]) + __bfloat162float(Pl[o]);
    }
    __shared__ float red[256];
    red[threadIdx.x] = sum; __syncthreads();
    for (int off = 128; off > 0; off >>= 1) {
        if (threadIdx.x < off) red[threadIdx.x] += red[threadIdx.x + off];
        __syncthreads();
    }
    if (threadIdx.x == 0) out[m] = red[0];
}

__global__ void __launch_bounds__(256) k_rowsum(const bf16* __restrict__ Ph,
                                                const bf16* __restrict__ Pl,
                                                float* __restrict__ v)
{
    const int m = blockIdx.y, r = blockIdx.x;
    const size_t o = (size_t)m * MM + (size_t)r * DN;
    float sum = 0.0f;
    for (int c = threadIdx.x; c < DN; c += 256)
        sum += __bfloat162float(Ph[o + c]) + __bfloat162float(Pl[o + c]);
    __shared__ float red[256];
    red[threadIdx.x] = sum; __syncthreads();
    for (int off = 128; off > 0; off >>= 1) {
        if (threadIdx.x < off) red[threadIdx.x] += red[threadIdx.x + off];
        __syncthreads();
    }
    if (threadIdx.x == 0) v[m * DN + r] = red[0];
}

__global__ void __launch_bounds__(256) k_matvec(const float* __restrict__ G,
                                                const float* __restrict__ v,
                                                float* __restrict__ gv)
{
    const int m = blockIdx.y, r = blockIdx.x;
    const float* row = G + (size_t)m * MM + (size_t)r * DN;
    const float* vm = v + m * DN;
    float4 a = *(const float4*)&row[threadIdx.x * 4];
    float4 b = *(const float4*)&vm[threadIdx.x * 4];
    float sum = a.x * b.x + a.y * b.y + a.z * b.z + a.w * b.w;
    __shared__ float red[256];
    red[threadIdx.x] = sum; __syncthreads();
    for (int off = 128; off > 0; off >>= 1) {
        if (threadIdx.x < off) red[threadIdx.x] += red[threadIdx.x + off];
        __syncthreads();
    }
    if (threadIdx.x == 0) gv[m * DN + r] = red[0];
}

__global__ void __launch_bounds__(256) k_sigma(const float* __restrict__ v,
                                               const float* __restrict__ gv,
                                               float* __restrict__ is_)
{
    const int m = blockIdx.x;
    float num = 0.0f, den = 0.0f;
    for (int d = threadIdx.x; d < DN; d += 256) {
        float vv = v[m * DN + d];
        num += vv * gv[m * DN + d];
        den += vv * vv;
    }
    __shared__ float rn[256], rd[256];
    rn[threadIdx.x] = num; rd[threadIdx.x] = den; __syncthreads();
    for (int off = 128; off > 0; off >>= 1) {
        if (threadIdx.x < off) { rn[threadIdx.x] += rn[threadIdx.x + off]; rd[threadIdx.x] += rd[threadIdx.x + off]; }
        __syncthreads();
    }
    if (threadIdx.x == 0) is_[m] = sqrtf(rd[0] / rn[0]);
}

// ---------------------------------------------------------------------------
extern "C" void kernel_launch(void* const* d_in, const int* in_sizes, int n_in,
                              void* d_out, int out_size)
{
    const float* x  = (const float*)d_in[0];
    const float* w1 = (const float*)d_in[1];
    const float* b1 = (const float*)d_in[2];
    const float* w2 = (const float*)d_in[3];
    const float* b2 = (const float*)d_in[4];
    float* out = (float*)d_out;

    bf16 *xhi, *xlo, *wth, *wtl, *P0h, *P0l, *P1h, *P1l, *hhi, *hlo;
    float *G, *tr, *v, *gv, *is_;
    cudaGetSymbolAddress((void**)&xhi, g_xhi); cudaGetSymbolAddress((void**)&xlo, g_xlo);
    cudaGetSymbolAddress((void**)&wth, g_wth); cudaGetSymbolAddress((void**)&wtl, g_wtl);
    cudaGetSymbolAddress((void**)&G, g_G);
    cudaGetSymbolAddress((void**)&P0h, g_P0h); cudaGetSymbolAddress((void**)&P0l, g_P0l);
    cudaGetSymbolAddress((void**)&P1h, g_P1h); cudaGetSymbolAddress((void**)&P1l, g_P1l);
    cudaGetSymbolAddress((void**)&hhi, g_hhi); cudaGetSymbolAddress((void**)&hlo, g_hlo);
    cudaGetSymbolAddress((void**)&tr, g_tr);   cudaGetSymbolAddress((void**)&v, g_v);
    cudaGetSymbolAddress((void**)&gv, g_gv);   cudaGetSymbolAddress((void**)&is_, g_is);

    cudaFuncSetAttribute(gemm_k<0>, cudaFuncAttributeMaxDynamicSharedMemorySize, SMEM_BYTES);
    cudaFuncSetAttribute(gemm_k<1>, cudaFuncAttributeMaxDynamicSharedMemorySize, SMEM_BYTES);
    cudaFuncSetAttribute(gemm_k<2>, cudaFuncAttributeMaxDynamicSharedMemorySize, SMEM_BYTES);
    cudaFuncSetAttribute(gemm_k<3>, cudaFuncAttributeMaxDynamicSharedMemorySize, SMEM_BYTES);

    conv_split<<<(unsigned)((size_t)BATCH * RS / 4 / 256), 256>>>(x, xhi, xlo);
    conv_wT<<<dim3(32, 32, NB), 256>>>(w1, wth, wtl);
    conv_wT<<<dim3(32, 32, NB), 256>>>(w2, wth + (size_t)NB * MM, wtl + (size_t)NB * MM);

    // Gram: G = W^T W (fp32 + hi/lo), then trace
    gemm_k<0><<<dim3(8, 8, NMAT), 256, SMEM_BYTES>>>(
        wth, wtl, DN, (long)MM, wth, wtl, G, P0h, P0l, DN, (long)MM,
        nullptr, nullptr, nullptr);
    k_trace_hl<<<NMAT, 256>>>(P0h, P0l, tr);

    // 12 trace-normalized squarings
    bf16 *pih = P0h, *pil = P0l, *poh = P1h, *pol = P1l;
    for (int s = 0; s < NSQ; s++) {
        gemm_k<1><<<dim3(8, 8, NMAT), 256, SMEM_BYTES>>>(
            pih, pil, DN, (long)MM, pih, pil, nullptr, poh, pol, DN, (long)MM,
            nullptr, nullptr, tr + s * NMAT);
        k_trace_hl<<<NMAT, 256>>>(poh, pol, tr + (s + 1) * NMAT);
        bf16* t1 = pih; pih = poh; poh = t1;
        bf16* t2 = pil; pil = pol; pol = t2;
    }

    // Rayleigh quotient on fp32 G with v = P_final @ 1
    k_rowsum<<<dim3(DN, NMAT), 256>>>(pih, pil, v);
    k_matvec<<<dim3(DN, NMAT), 256>>>(G, v, gv);
    k_sigma<<<NMAT, 256>>>(v, gv, is_);

    // MLP
    gemm_k<2><<<dim3(8, 32, NB), 256, SMEM_BYTES>>>(
        xhi, xlo, RS, (long)DN, wth, wtl, nullptr, hhi, hlo, RS, (long)DN,
        b1, is_, nullptr);
    gemm_k<3><<<dim3(8, 32, NB), 256, SMEM_BYTES>>>(
        hhi, hlo, RS, (long)DN, wth + (size_t)NB * MM, wtl + (size_t)NB * MM,
        out, nullptr, nullptr, RS, (long)DN, b2, is_ + NB, nullptr);
}

// round 6
// speedup vs baseline: 3.7662x; 1.9115x over previous
#include <cuda_runtime.h>
#include <cuda_bf16.h>
#include <cstdint>
#include <math.h>

#define NB 25
#define BATCH 4096
#define DN 1024
#define RS (NB * DN)
#define NMAT (2 * NB)
#define MM ((size_t)DN * DN)
#define NSQ 10
#define BK 64
#define NKS (DN / BK)          // 16 k-stages
#define RSEB 144               // smem row stride bytes (128B data + 16B pad)
#define MATB (128 * RSEB)      // 18432 B per matrix tile
#define STGB (4 * MATB)        // 73728 B per stage
#define SMEM_BYTES (2 * STGB)  // 147456

typedef __nv_bfloat16 bf16;

// ----------------------------- scratch -------------------------------------
__device__ bf16  g_xhi[(size_t)BATCH * RS];
__device__ bf16  g_xlo[(size_t)BATCH * RS];
__device__ bf16  g_wth[NMAT * MM];
__device__ bf16  g_wtl[NMAT * MM];
__device__ float g_G  [NMAT * MM];
__device__ bf16  g_P0h[NMAT * MM];
__device__ bf16  g_P0l[NMAT * MM];
__device__ bf16  g_P1h[NMAT * MM];
__device__ bf16  g_P1l[NMAT * MM];
__device__ bf16  g_hhi[(size_t)BATCH * RS];
__device__ bf16  g_hlo[(size_t)BATCH * RS];
__device__ float g_tr [(NSQ + 1) * NMAT];
__device__ float g_v  [NMAT * DN];
__device__ float g_gv [NMAT * DN];
__device__ float g_is [NMAT];

// ----------------------------- PTX helpers ---------------------------------
__device__ __forceinline__ uint32_t smem_u32(const void* p) {
    uint32_t a;
    asm("{ .reg .u64 t; cvta.to.shared.u64 t, %1; cvt.u32.u64 %0, t; }" : "=r"(a) : "l"(p));
    return a;
}
__device__ __forceinline__ void cp16(uint32_t s, const void* g) {
    asm volatile("cp.async.cg.shared.global [%0], [%1], 16;" :: "r"(s), "l"(g));
}
#define CP_COMMIT() asm volatile("cp.async.commit_group;" ::: "memory")
#define CP_WAIT(N)  asm volatile("cp.async.wait_group %0;" :: "n"(N) : "memory")

#define LDSM4(r0, r1, r2, r3, addr) \
    asm volatile("ldmatrix.sync.aligned.m8n8.x4.shared.b16 {%0,%1,%2,%3}, [%4];" \
        : "=r"(r0), "=r"(r1), "=r"(r2), "=r"(r3) : "r"(addr))

#define MMA16816(c, a, b) \
    asm volatile("mma.sync.aligned.m16n8k16.row.col.f32.bf16.bf16.f32 " \
        "{%0,%1,%2,%3}, {%4,%5,%6,%7}, {%8,%9}, {%0,%1,%2,%3};" \
        : "+f"((c)[0]), "+f"((c)[1]), "+f"((c)[2]), "+f"((c)[3]) \
        : "r"((a)[0]), "r"((a)[1]), "r"((a)[2]), "r"((a)[3]), "r"((b)[0]), "r"((b)[1]))

// ----------------------------- conversions ---------------------------------
__global__ void __launch_bounds__(256) conv_split(const float* __restrict__ in,
                                                  bf16* __restrict__ hi, bf16* __restrict__ lo)
{
    size_t i = ((size_t)blockIdx.x * 256 + threadIdx.x) * 4;
    float4 v = *(const float4*)(in + i);
    bf16 h0 = __float2bfloat16(v.x), h1 = __float2bfloat16(v.y);
    bf16 h2 = __float2bfloat16(v.z), h3 = __float2bfloat16(v.w);
    hi[i+0] = h0; hi[i+1] = h1; hi[i+2] = h2; hi[i+3] = h3;
    lo[i+0] = __float2bfloat16(v.x - __bfloat162float(h0));
    lo[i+1] = __float2bfloat16(v.y - __bfloat162float(h1));
    lo[i+2] = __float2bfloat16(v.z - __bfloat162float(h2));
    lo[i+3] = __float2bfloat16(v.w - __bfloat162float(h3));
}

__global__ void __launch_bounds__(256) conv_wT(const float* __restrict__ w,
                                               bf16* __restrict__ hi, bf16* __restrict__ lo)
{
    const int m = blockIdx.z;
    const float* W = w + (size_t)m * MM;
    bf16* Hi = hi + (size_t)m * MM;
    bf16* Lo = lo + (size_t)m * MM;
    __shared__ float t[32][33];
    const int r0 = blockIdx.y * 32, c0 = blockIdx.x * 32;
    const int tr = threadIdx.x >> 5, tc = threadIdx.x & 31;
#pragma unroll
    for (int i = 0; i < 4; i++)
        t[tr + 8 * i][tc] = W[(size_t)(r0 + tr + 8 * i) * DN + c0 + tc];
    __syncthreads();
#pragma unroll
    for (int i = 0; i < 4; i++) {
        int rr = tr + 8 * i;
        float v = t[tc][rr];
        bf16 h = __float2bfloat16(v);
        size_t o = (size_t)(c0 + rr) * DN + r0 + tc;
        Hi[o] = h;
        Lo[o] = __float2bfloat16(v - __bfloat162float(h));
    }
}

// ----------------------------- warp-MMA GEMM --------------------------------
// C[r][c] = scl * sum_k A[r][k] * B[c][k]   (both operands K-major)
// MODE 0: Gram   -> Cf (fp32) + Chi/Clo   [symmetric: triangular grid + mirror]
// MODE 1: square -> Chi/Clo, scl=(1/tr)^2 [symmetric: triangular grid + mirror]
// MODE 2: MLP1   -> Chi/Clo = gelu(C*is + b1)
// MODE 3: MLP2   -> Cf = C*is + b2
template <int MODE>
__global__ void __launch_bounds__(256, 1) gemm_k(
    const bf16* __restrict__ Ahi, const bf16* __restrict__ Alo, long lda, long aoffz,
    const bf16* __restrict__ Bhi, const bf16* __restrict__ Blo,
    float* __restrict__ Cf, bf16* __restrict__ Chi, bf16* __restrict__ Clo,
    long ldc, long coffz,
    const float* __restrict__ bias, const float* __restrict__ sc,
    const float* __restrict__ trin)
{
    extern __shared__ char smem[];
    const uint32_t sb = smem_u32(smem);

    const int tid = threadIdx.x;
    const int wid = tid >> 5, lane = tid & 31;
    const int wr = wid >> 1, wc = wid & 1;
    const int z = blockIdx.z;

    int row0, col0;
    if (MODE <= 1) {
        int t = blockIdx.x, ti = 0;
        while (t >= 8 - ti) { t -= 8 - ti; ti++; }
        row0 = ti * 128; col0 = (ti + t) * 128;
    } else {
        row0 = blockIdx.y * 128; col0 = blockIdx.x * 128;
    }

    const bf16* Ah = Ahi + (size_t)z * aoffz + (size_t)row0 * lda;
    const bf16* Al = Alo + (size_t)z * aoffz + (size_t)row0 * lda;
    const bf16* Bh = Bhi + (size_t)z * MM + (size_t)col0 * DN;
    const bf16* Bl = Blo + (size_t)z * MM + (size_t)col0 * DN;

    const bf16* gbase[4] = {Ah, Al, Bh, Bl};
    const long  gstr [4] = {lda, lda, DN, DN};

    // stage loader: 4 matrices x 128 rows x 64 bf16 (128B) each
    auto load_stage = [&](int st, int k0) {
        const uint32_t base = sb + (uint32_t)st * STGB;
        const int ch = tid & 7;                   // 16B chunk
        const int rlo = tid >> 3;                 // 0..31
#pragma unroll
        for (int t = 0; t < 16; t++) {
            const int mat = t >> 2;
            const int r = ((t & 3) << 5) + rlo;   // 0..127
            cp16(base + (uint32_t)mat * MATB + (uint32_t)(r * RSEB + ch * 16),
                 gbase[mat] + (long)r * gstr[mat] + k0 + ch * 8);
        }
        CP_COMMIT();
    };

    float acc[2][8][4];
#pragma unroll
    for (int mi = 0; mi < 2; mi++)
#pragma unroll
        for (int ni = 0; ni < 8; ni++)
#pragma unroll
            for (int q = 0; q < 4; q++) acc[mi][ni][q] = 0.0f;

    load_stage(0, 0);

    const int arow = (lane & 7) + ((lane >> 3) & 1) * 8;
    const int acol = (lane >> 4) * 16;            // bytes
    const int brow = (lane & 7) + ((lane >> 4) & 1) * 8;
    const int bcol = ((lane >> 3) & 1) * 16;      // bytes

    for (int s = 0; s < NKS; s++) {
        CP_WAIT(0);
        __syncthreads();
        if (s + 1 < NKS) load_stage((s + 1) & 1, (s + 1) * BK);

        const uint32_t stb = sb + (uint32_t)(s & 1) * STGB;
        const uint32_t aBh = stb + (uint32_t)((wr * 32 + arow) * RSEB) + acol;
        const uint32_t aBl = aBh + MATB;
        const uint32_t bBh = stb + 2u * MATB + (uint32_t)((wc * 64 + brow) * RSEB) + bcol;
        const uint32_t bBl = bBh + MATB;

#pragma unroll
        for (int kk = 0; kk < 4; kk++) {
            const uint32_t ko = (uint32_t)(kk * 32);   // 16 bf16 = 32B
            uint32_t ah[2][4], al[2][4], bh[8][2], bl[8][2];
#pragma unroll
            for (int mi = 0; mi < 2; mi++) {
                LDSM4(ah[mi][0], ah[mi][1], ah[mi][2], ah[mi][3], aBh + ko + (uint32_t)(mi * 16 * RSEB));
                LDSM4(al[mi][0], al[mi][1], al[mi][2], al[mi][3], aBl + ko + (uint32_t)(mi * 16 * RSEB));
            }
#pragma unroll
            for (int p = 0; p < 4; p++) {
                LDSM4(bh[2*p][0], bh[2*p][1], bh[2*p+1][0], bh[2*p+1][1], bBh + ko + (uint32_t)(p * 16 * RSEB));
                LDSM4(bl[2*p][0], bl[2*p][1], bl[2*p+1][0], bl[2*p+1][1], bBl + ko + (uint32_t)(p * 16 * RSEB));
            }
#pragma unroll
            for (int mi = 0; mi < 2; mi++)
#pragma unroll
                for (int ni = 0; ni < 8; ni++) MMA16816(acc[mi][ni], ah[mi], bh[ni]);
#pragma unroll
            for (int mi = 0; mi < 2; mi++)
#pragma unroll
                for (int ni = 0; ni < 8; ni++) MMA16816(acc[mi][ni], ah[mi], bl[ni]);
#pragma unroll
            for (int mi = 0; mi < 2; mi++)
#pragma unroll
                for (int ni = 0; ni < 8; ni++) MMA16816(acc[mi][ni], al[mi], bh[ni]);
        }
        __syncthreads();
    }

    // ------------------------------ epilogue -------------------------------
    float scl = 1.0f;
    if (MODE == 1) { float it = 1.0f / trin[z]; scl = it * it; }
    if (MODE >= 2) scl = sc[z];
    const int gID = lane >> 2, tg = lane & 3;
    const bool mirror = (MODE <= 1) && (row0 != col0);
    float* ts = (float*)smem;

#pragma unroll
    for (int mi = 0; mi < 2; mi++)
#pragma unroll
        for (int ni = 0; ni < 8; ni++)
#pragma unroll
            for (int hf = 0; hf < 2; hf++) {
                const int rl = wr * 32 + mi * 16 + gID + hf * 8;
                const int cl = wc * 64 + ni * 8 + tg * 2;
                float v0 = acc[mi][ni][hf * 2 + 0] * scl;
                float v1 = acc[mi][ni][hf * 2 + 1] * scl;
                if (MODE >= 2) {
                    v0 += bias[z * DN + col0 + cl];
                    v1 += bias[z * DN + col0 + cl + 1];
                }
                if (MODE == 2) {
                    v0 = 0.5f * v0 * (1.0f + erff(v0 * 0.70710678118654752f));
                    v1 = 0.5f * v1 * (1.0f + erff(v1 * 0.70710678118654752f));
                }
                const size_t off = (size_t)z * coffz + (size_t)(row0 + rl) * ldc + col0 + cl;
                if (MODE == 0 || MODE == 3) {
                    float2 f2; f2.x = v0; f2.y = v1;
                    *(float2*)(Cf + off) = f2;
                }
                if (MODE <= 2) {
                    bf16 h0 = __float2bfloat16(v0);
                    bf16 h1 = __float2bfloat16(v1);
                    __nv_bfloat162 hh; hh.x = h0; hh.y = h1;
                    __nv_bfloat162 ll;
                    ll.x = __float2bfloat16(v0 - __bfloat162float(h0));
                    ll.y = __float2bfloat16(v1 - __bfloat162float(h1));
                    *(__nv_bfloat162*)(Chi + off) = hh;
                    *(__nv_bfloat162*)(Clo + off) = ll;
                }
                if (mirror) {
                    ts[rl * 129 + cl] = v0;
                    ts[rl * 129 + cl + 1] = v1;
                }
            }

    // mirror tile: write transpose at (col0, row0), coalesced along row0+mc
    if (mirror) {
        __syncthreads();
#pragma unroll 4
        for (int i = 0; i < 32; i++) {
            int lin = i * 512 + tid * 2;
            int mr = lin >> 7, mc = lin & 127;
            float v0 = ts[mc * 129 + mr];
            float v1 = ts[(mc + 1) * 129 + mr];
            const size_t off = (size_t)z * coffz + (size_t)(col0 + mr) * ldc + row0 + mc;
            if (MODE == 0) {
                float2 f2; f2.x = v0; f2.y = v1;
                *(float2*)(Cf + off) = f2;
            }
            bf16 h0 = __float2bfloat16(v0);
            bf16 h1 = __float2bfloat16(v1);
            __nv_bfloat162 hh; hh.x = h0; hh.y = h1;
            __nv_bfloat162 ll;
            ll.x = __float2bfloat16(v0 - __bfloat162float(h0));
            ll.y = __float2bfloat16(v1 - __bfloat162float(h1));
            *(__nv_bfloat162*)(Chi + off) = hh;
            *(__nv_bfloat162*)(Clo + off) = ll;
        }
    }
}

// --------------------------- small kernels ----------------------------------
__global__ void __launch_bounds__(256) k_trace_hl(const bf16* __restrict__ Ph,
                                                  const bf16* __restrict__ Pl,
                                                  float* __restrict__ out)
{
    const int m = blockIdx.x;
    float sum = 0.0f;
    for (int d = threadIdx.x; d < DN; d += 256) {
        size_t o = (size_t)m * MM + (size_t)d * DN + d;
        sum += __bfloat162float(Ph[o]) + __bfloat162float(Pl[o]);
    }
    __shared__ float red[256];
    red[threadIdx.x] = sum; __syncthreads();
    for (int off = 128; off > 0; off >>= 1) {
        if (threadIdx.x < off) red[threadIdx.x] += red[threadIdx.x + off];
        __syncthreads();
    }
    if (threadIdx.x == 0) out[m] = red[0];
}

__global__ void __launch_bounds__(256) k_rowsum(const bf16* __restrict__ Ph,
                                                const bf16* __restrict__ Pl,
                                                float* __restrict__ v)
{
    const int m = blockIdx.y, r = blockIdx.x;
    const size_t o = (size_t)m * MM + (size_t)r * DN;
    float sum = 0.0f;
    for (int c = threadIdx.x; c < DN; c += 256)
        sum += __bfloat162float(Ph[o + c]) + __bfloat162float(Pl[o + c]);
    __shared__ float red[256];
    red[threadIdx.x] = sum; __syncthreads();
    for (int off = 128; off > 0; off >>= 1) {
        if (threadIdx.x < off) red[threadIdx.x] += red[threadIdx.x + off];
        __syncthreads();
    }
    if (threadIdx.x == 0) v[m * DN + r] = red[0];
}

__global__ void __launch_bounds__(256) k_matvec(const float* __restrict__ G,
                                                const float* __restrict__ v,
                                                float* __restrict__ gv)
{
    const int m = blockIdx.y, r = blockIdx.x;
    const float* row = G + (size_t)m * MM + (size_t)r * DN;
    const float* vm = v + m * DN;
    float4 a = *(const float4*)&row[threadIdx.x * 4];
    float4 b = *(const float4*)&vm[threadIdx.x * 4];
    float sum = a.x * b.x + a.y * b.y + a.z * b.z + a.w * b.w;
    __shared__ float red[256];
    red[threadIdx.x] = sum; __syncthreads();
    for (int off = 128; off > 0; off >>= 1) {
        if (threadIdx.x < off) red[threadIdx.x] += red[threadIdx.x + off];
        __syncthreads();
    }
    if (threadIdx.x == 0) gv[m * DN + r] = red[0];
}

__global__ void __launch_bounds__(256) k_sigma(const float* __restrict__ v,
                                               const float* __restrict__ gv,
                                               float* __restrict__ is_)
{
    const int m = blockIdx.x;
    float num = 0.0f, den = 0.0f;
    for (int d = threadIdx.x; d < DN; d += 256) {
        float vv = v[m * DN + d];
        num += vv * gv[m * DN + d];
        den += vv * vv;
    }
    __shared__ float rn[256], rd[256];
    rn[threadIdx.x] = num; rd[threadIdx.x] = den; __syncthreads();
    for (int off = 128; off > 0; off >>= 1) {
        if (threadIdx.x < off) { rn[threadIdx.x] += rn[threadIdx.x + off]; rd[threadIdx.x] += rd[threadIdx.x + off]; }
        __syncthreads();
    }
    if (threadIdx.x == 0) is_[m] = sqrtf(rd[0] / rn[0]);
}

// ---------------------------------------------------------------------------
extern "C" void kernel_launch(void* const* d_in, const int* in_sizes, int n_in,
                              void* d_out, int out_size)
{
    const float* x  = (const float*)d_in[0];
    const float* w1 = (const float*)d_in[1];
    const float* b1 = (const float*)d_in[2];
    const float* w2 = (const float*)d_in[3];
    const float* b2 = (const float*)d_in[4];
    float* out = (float*)d_out;

    bf16 *xhi, *xlo, *wth, *wtl, *P0h, *P0l, *P1h, *P1l, *hhi, *hlo;
    float *G, *tr, *v, *gv, *is_;
    cudaGetSymbolAddress((void**)&xhi, g_xhi); cudaGetSymbolAddress((void**)&xlo, g_xlo);
    cudaGetSymbolAddress((void**)&wth, g_wth); cudaGetSymbolAddress((void**)&wtl, g_wtl);
    cudaGetSymbolAddress((void**)&G, g_G);
    cudaGetSymbolAddress((void**)&P0h, g_P0h); cudaGetSymbolAddress((void**)&P0l, g_P0l);
    cudaGetSymbolAddress((void**)&P1h, g_P1h); cudaGetSymbolAddress((void**)&P1l, g_P1l);
    cudaGetSymbolAddress((void**)&hhi, g_hhi); cudaGetSymbolAddress((void**)&hlo, g_hlo);
    cudaGetSymbolAddress((void**)&tr, g_tr);   cudaGetSymbolAddress((void**)&v, g_v);
    cudaGetSymbolAddress((void**)&gv, g_gv);   cudaGetSymbolAddress((void**)&is_, g_is);

    cudaFuncSetAttribute(gemm_k<0>, cudaFuncAttributeMaxDynamicSharedMemorySize, SMEM_BYTES);
    cudaFuncSetAttribute(gemm_k<1>, cudaFuncAttributeMaxDynamicSharedMemorySize, SMEM_BYTES);
    cudaFuncSetAttribute(gemm_k<2>, cudaFuncAttributeMaxDynamicSharedMemorySize, SMEM_BYTES);
    cudaFuncSetAttribute(gemm_k<3>, cudaFuncAttributeMaxDynamicSharedMemorySize, SMEM_BYTES);

    conv_split<<<(unsigned)((size_t)BATCH * RS / 4 / 256), 256>>>(x, xhi, xlo);
    conv_wT<<<dim3(32, 32, NB), 256>>>(w1, wth, wtl);
    conv_wT<<<dim3(32, 32, NB), 256>>>(w2, wth + (size_t)NB * MM, wtl + (size_t)NB * MM);

    // Gram: G = W^T W (fp32 + hi/lo), triangular grid, then trace
    gemm_k<0><<<dim3(36, 1, NMAT), 256, SMEM_BYTES>>>(
        wth, wtl, DN, (long)MM, wth, wtl, G, P0h, P0l, DN, (long)MM,
        nullptr, nullptr, nullptr);
    k_trace_hl<<<NMAT, 256>>>(P0h, P0l, tr);

    // trace-normalized squarings (triangular + mirror)
    bf16 *pih = P0h, *pil = P0l, *poh = P1h, *pol = P1l;
    for (int s = 0; s < NSQ; s++) {
        gemm_k<1><<<dim3(36, 1, NMAT), 256, SMEM_BYTES>>>(
            pih, pil, DN, (long)MM, pih, pil, nullptr, poh, pol, DN, (long)MM,
            nullptr, nullptr, tr + s * NMAT);
        k_trace_hl<<<NMAT, 256>>>(poh, pol, tr + (s + 1) * NMAT);
        bf16* t1 = pih; pih = poh; poh = t1;
        bf16* t2 = pil; pil = pol; pol = t2;
    }

    // Rayleigh quotient on fp32 G with v = P_final @ 1
    k_rowsum<<<dim3(DN, NMAT), 256>>>(pih, pil, v);
    k_matvec<<<dim3(DN, NMAT), 256>>>(G, v, gv);
    k_sigma<<<NMAT, 256>>>(v, gv, is_);

    // MLP
    gemm_k<2><<<dim3(8, 32, NB), 256, SMEM_BYTES>>>(
        xhi, xlo, RS, (long)DN, wth, wtl, nullptr, hhi, hlo, RS, (long)DN,
        b1, is_, nullptr);
    gemm_k<3><<<dim3(8, 32, NB), 256, SMEM_BYTES>>>(
        hhi, hlo, RS, (long)DN, wth + (size_t)NB * MM, wtl + (size_t)NB * MM,
        out, nullptr, nullptr, RS, (long)DN, b2, is_ + NB, nullptr);
}